// round 1
// baseline (speedup 1.0000x reference)
#include <cuda_runtime.h>
#include <math.h>

// Problem constants (fixed by the reference)
#define S_LEN   2048
#define BATCH   2
#define DMODEL  1024
#define NHEAD   16
#define DHEAD   64
#define MROWS   (S_LEN * BATCH)   // 4096 rows for the projection GEMMs

// Scratch: __device__ globals (no allocation allowed). 4 x 16MB = 64MB.
__device__ float g_q[S_LEN * BATCH * DMODEL];
__device__ float g_k[S_LEN * BATCH * DMODEL];
__device__ float g_v[S_LEN * BATCH * DMODEL];
__device__ float g_attn[S_LEN * BATCH * DMODEL];

// ---------------------------------------------------------------------------
// Y[m,n] = sum_k X[m,k] * W[n,k] + bias[n]
// X: [M,K] row-major, W: [N,K] row-major (i.e. Y = X @ W^T + b)
// 64x64 tile, BK=16, 256 threads, 4x4 per-thread micro-tile.
// M=4096, N=K=1024 -> all tile-divisible, no bounds checks.
// ---------------------------------------------------------------------------
__global__ void __launch_bounds__(256)
gemm_bias_kernel(const float* __restrict__ X, const float* __restrict__ W,
                 const float* __restrict__ bias, float* __restrict__ Y,
                 int M, int N, int K)
{
    const int BM = 64, BN = 64, BK = 16;
    __shared__ __align__(16) float Xs[BK][BM + 4];  // [k][m], padded
    __shared__ __align__(16) float Ws[BK][BN + 4];  // [k][n], padded

    const int tid = threadIdx.x;
    const int tx  = tid & 15;        // 0..15 -> 4 output cols each
    const int ty  = tid >> 4;        // 0..15 -> 4 output rows each
    const int m0  = blockIdx.y * BM;
    const int n0  = blockIdx.x * BN;

    // Staged-load mapping: thread -> one float4 of X tile and one of W tile.
    const int lr = tid >> 2;         // 0..63  (row within tile)
    const int lc = (tid & 3) * 4;    // 0,4,8,12 (k offset)

    float acc[4][4] = {};

    for (int k0 = 0; k0 < K; k0 += BK) {
        float4 xa = *(const float4*)(X + (size_t)(m0 + lr) * K + k0 + lc);
        float4 wa = *(const float4*)(W + (size_t)(n0 + lr) * K + k0 + lc);
        Xs[lc + 0][lr] = xa.x; Xs[lc + 1][lr] = xa.y;
        Xs[lc + 2][lr] = xa.z; Xs[lc + 3][lr] = xa.w;
        Ws[lc + 0][lr] = wa.x; Ws[lc + 1][lr] = wa.y;
        Ws[lc + 2][lr] = wa.z; Ws[lc + 3][lr] = wa.w;
        __syncthreads();

        #pragma unroll
        for (int k = 0; k < BK; k++) {
            float4 a4 = *(const float4*)&Xs[k][ty * 4];
            float4 b4 = *(const float4*)&Ws[k][tx * 4];
            float a[4] = {a4.x, a4.y, a4.z, a4.w};
            float b[4] = {b4.x, b4.y, b4.z, b4.w};
            #pragma unroll
            for (int i = 0; i < 4; i++)
                #pragma unroll
                for (int j = 0; j < 4; j++)
                    acc[i][j] += a[i] * b[j];
        }
        __syncthreads();
    }

    #pragma unroll
    for (int i = 0; i < 4; i++) {
        const int m = m0 + ty * 4 + i;
        float* yrow = Y + (size_t)m * N + n0 + tx * 4;
        float4 bv = *(const float4*)(bias + n0 + tx * 4);
        float4 r;
        r.x = acc[i][0] + bv.x;
        r.y = acc[i][1] + bv.y;
        r.z = acc[i][2] + bv.z;
        r.w = acc[i][3] + bv.w;
        *(float4*)yrow = r;
    }
}

// ---------------------------------------------------------------------------
// Flash-attention over projected q/k/v stored as [S, B, D] with D = H*DK.
// One thread owns one query row (q and o accumulator register-resident).
// Block: 128 threads = 128 query rows for one (h, b).
// K/V streamed through smem in 64-key tiles. Online softmax with lazy rescale.
// Output written back in [S, B, D] layout (heads re-interleaved) so the final
// projection is a plain GEMM.
// ---------------------------------------------------------------------------
__global__ void __launch_bounds__(128)
attn_kernel(const float* __restrict__ Q, const float* __restrict__ Kp,
            const float* __restrict__ Vp, float* __restrict__ O)
{
    const int t    = threadIdx.x;
    const int qrow = blockIdx.x * 128 + t;
    const int hb   = blockIdx.y;
    const int h    = hb >> 1;        // BATCH = 2
    const int b    = hb & 1;

    const size_t head_off = (size_t)h * DHEAD;

    // Load q row into registers
    float q[DHEAD];
    {
        const float* qp = Q + ((size_t)qrow * BATCH + b) * DMODEL + head_off;
        #pragma unroll
        for (int i = 0; i < DHEAD / 4; i++) {
            float4 v4 = *(const float4*)(qp + i * 4);
            q[4*i + 0] = v4.x; q[4*i + 1] = v4.y;
            q[4*i + 2] = v4.z; q[4*i + 3] = v4.w;
        }
    }

    float o[DHEAD];
    #pragma unroll
    for (int i = 0; i < DHEAD; i++) o[i] = 0.0f;
    float m = -1e30f;
    float l = 0.0f;
    const float scale = 0.125f;  // 1/sqrt(64)

    __shared__ __align__(16) float Ks[64][DHEAD];
    __shared__ __align__(16) float Vs[64][DHEAD];

    for (int kb = 0; kb < S_LEN; kb += 64) {
        __syncthreads();  // protect smem from previous tile's readers
        // Cooperative load: warp-coalesced (2 rows x 16 float4 per warp step)
        {
            const int f  = (t & 15) * 4;      // float offset within row
            const int r0 = t >> 4;            // starting row, stride 8
            #pragma unroll
            for (int rr = 0; rr < 8; rr++) {
                const int r = r0 + rr * 8;
                const size_t gofs = ((size_t)(kb + r) * BATCH + b) * DMODEL + head_off + f;
                *(float4*)&Ks[r][f] = *(const float4*)(Kp + gofs);
                *(float4*)&Vs[r][f] = *(const float4*)(Vp + gofs);
            }
        }
        __syncthreads();

        #pragma unroll 4
        for (int j = 0; j < 64; j++) {
            float s = 0.0f;
            #pragma unroll
            for (int d = 0; d < DHEAD; d++)
                s += q[d] * Ks[j][d];
            s *= scale;

            if (s > m) {
                // new running max: rescale (rare: ~ln(S) times per row)
                const float corr = __expf(m - s);
                m = s;
                l = l * corr + 1.0f;
                #pragma unroll
                for (int d = 0; d < DHEAD; d++)
                    o[d] = o[d] * corr + Vs[j][d];
            } else {
                const float p = __expf(s - m);
                l += p;
                #pragma unroll
                for (int d = 0; d < DHEAD; d++)
                    o[d] += p * Vs[j][d];
            }
        }
    }

    const float inv = 1.0f / l;
    float* op = O + ((size_t)qrow * BATCH + b) * DMODEL + head_off;
    #pragma unroll
    for (int i = 0; i < DHEAD / 4; i++) {
        float4 r;
        r.x = o[4*i + 0] * inv; r.y = o[4*i + 1] * inv;
        r.z = o[4*i + 2] * inv; r.w = o[4*i + 3] * inv;
        *(float4*)(op + i * 4) = r;
    }
}

// ---------------------------------------------------------------------------
extern "C" void kernel_launch(void* const* d_in, const int* in_sizes, int n_in,
                              void* d_out, int out_size)
{
    (void)in_sizes; (void)n_in; (void)out_size;
    const float* query = (const float*)d_in[0];
    const float* key   = (const float*)d_in[1];
    const float* value = (const float*)d_in[2];
    const float* Wq    = (const float*)d_in[3];
    const float* bq    = (const float*)d_in[4];
    const float* Wk    = (const float*)d_in[5];
    const float* bk    = (const float*)d_in[6];
    const float* Wv    = (const float*)d_in[7];
    const float* bv    = (const float*)d_in[8];
    const float* Wo    = (const float*)d_in[9];
    const float* bo    = (const float*)d_in[10];
    float* out = (float*)d_out;

    float *qp, *kp, *vp, *ap;
    cudaGetSymbolAddress((void**)&qp, g_q);
    cudaGetSymbolAddress((void**)&kp, g_k);
    cudaGetSymbolAddress((void**)&vp, g_v);
    cudaGetSymbolAddress((void**)&ap, g_attn);

    dim3 gblk(256);
    dim3 ggrid(DMODEL / 64, MROWS / 64);   // (16, 64)

    gemm_bias_kernel<<<ggrid, gblk>>>(query, Wq, bq, qp, MROWS, DMODEL, DMODEL);
    gemm_bias_kernel<<<ggrid, gblk>>>(key,   Wk, bk, kp, MROWS, DMODEL, DMODEL);
    gemm_bias_kernel<<<ggrid, gblk>>>(value, Wv, bv, vp, MROWS, DMODEL, DMODEL);

    dim3 agrid(S_LEN / 128, NHEAD * BATCH);  // (16, 32)
    attn_kernel<<<agrid, 128>>>(qp, kp, vp, ap);

    gemm_bias_kernel<<<ggrid, gblk>>>(ap, Wo, bo, out, MROWS, DMODEL, DMODEL);
}